// round 9
// baseline (speedup 1.0000x reference)
#include <cuda_runtime.h>
#include <cuda_bf16.h>
#include <cstdint>

// Problem constants
#define B_   2
#define N_   4096
#define E_   256
#define H_   8
#define TAU_ 32
#define HD_  32
#define M_   (B_ * N_)
#define SCALING 0.17677669529663687f

#define XSZ  ((size_t)M_ * E_)          // 2,097,152 elems per tensor
#define WOFF (3 * XSZ)                  // W offset in bf16 scratch
#define TOT_ELEMS (3 * XSZ + (size_t)E_ * E_)

// Scratch
__device__ float g_proj[3 * XSZ];                         // projected Q,K,V fp32
__device__ __align__(16) __nv_bfloat16 g_h[TOT_ELEMS];    // bf16 hi of Q,K,V,W
__device__ __align__(16) __nv_bfloat16 g_l[TOT_ELEMS];    // bf16 lo residual

// ---------------------------------------------------------------------------
__device__ __forceinline__ void mma_bf16(float c[4], const uint32_t a[4],
                                         const uint32_t b[2]) {
    asm volatile(
        "mma.sync.aligned.m16n8k16.row.col.f32.bf16.bf16.f32 "
        "{%0,%1,%2,%3}, {%4,%5,%6,%7}, {%8,%9}, {%0,%1,%2,%3};"
        : "+f"(c[0]), "+f"(c[1]), "+f"(c[2]), "+f"(c[3])
        : "r"(a[0]), "r"(a[1]), "r"(a[2]), "r"(a[3]), "r"(b[0]), "r"(b[1]));
}

// ---------------------------------------------------------------------------
// Conversion pass: fp32 -> bf16 hi + bf16 lo residual, for Q,K,V,W.
// Pure streaming, ~51 MB of HBM traffic.
// ---------------------------------------------------------------------------
__global__ __launch_bounds__(256) void convert_kernel(
        const float* __restrict__ Q, const float* __restrict__ K,
        const float* __restrict__ V, const float* __restrict__ W) {
    size_t i = (size_t)blockIdx.x * 256 + threadIdx.x;   // float4 index
    const size_t X4 = XSZ / 4;
    const size_t T4 = TOT_ELEMS / 4;
    if (i >= T4) return;
    const float* src;
    if      (i <     X4) src = Q + 4 * i;
    else if (i < 2 * X4) src = K + 4 * (i - X4);
    else if (i < 3 * X4) src = V + 4 * (i - 2 * X4);
    else                 src = W + 4 * (i - 3 * X4);
    float4 v = *reinterpret_cast<const float4*>(src);
    __nv_bfloat16 h0 = __float2bfloat16(v.x);
    __nv_bfloat16 h1 = __float2bfloat16(v.y);
    __nv_bfloat16 h2 = __float2bfloat16(v.z);
    __nv_bfloat16 h3 = __float2bfloat16(v.w);
    __nv_bfloat16 l0 = __float2bfloat16(v.x - __bfloat162float(h0));
    __nv_bfloat16 l1 = __float2bfloat16(v.y - __bfloat162float(h1));
    __nv_bfloat16 l2 = __float2bfloat16(v.z - __bfloat162float(h2));
    __nv_bfloat16 l3 = __float2bfloat16(v.w - __bfloat162float(h3));
    *reinterpret_cast<ushort4*>(&g_h[4 * i]) =
        make_ushort4(__bfloat16_as_ushort(h0), __bfloat16_as_ushort(h1),
                     __bfloat16_as_ushort(h2), __bfloat16_as_ushort(h3));
    *reinterpret_cast<ushort4*>(&g_l[4 * i]) =
        make_ushort4(__bfloat16_as_ushort(l0), __bfloat16_as_ushort(l1),
                     __bfloat16_as_ushort(l2), __bfloat16_as_ushort(l3));
}

// ---------------------------------------------------------------------------
// Projection GEMM: P = X @ W^T + bias (M=8192, N=256, K=256), z selects X.
// Block 128x64, BK=32, 8 warps (4M x 2N), warp tile 32x32, split-3 bf16.
// Staging = pure uint4 (16B = 8 bf16) copies from preconverted g_h/g_l.
// SST=40: 16B-aligned stores AND conflict-free fragment LDS (word stride 20
// tiles all 32 banks exactly: banks {20g mod 32}+tig, g=0..7, tig=0..3).
// ---------------------------------------------------------------------------
#define SST 40   // smem row stride in bf16 elems (32 + 8 pad)

__global__ __launch_bounds__(256) void proj_kernel(const float* __restrict__ bias) {
    __shared__ alignas(16) __nv_bfloat16 sAh[128 * SST];
    __shared__ alignas(16) __nv_bfloat16 sAl[128 * SST];
    __shared__ alignas(16) __nv_bfloat16 sBh[64 * SST];
    __shared__ alignas(16) __nv_bfloat16 sBl[64 * SST];

    const size_t xoff = (size_t)blockIdx.z * XSZ;
    float* P = g_proj + xoff;

    const int tid  = threadIdx.x;
    const int m0   = blockIdx.y << 7;
    const int n0   = blockIdx.x << 6;
    const int lane = tid & 31;
    const int warp = tid >> 5;
    const int g    = lane >> 2;
    const int tig  = lane & 3;
    const int wM   = warp & 3;
    const int wN   = warp >> 2;

    float acc[2][4][4];
    #pragma unroll
    for (int mi = 0; mi < 2; mi++)
        #pragma unroll
        for (int ni = 0; ni < 4; ni++)
            #pragma unroll
            for (int r = 0; r < 4; r++) acc[mi][ni][r] = 0.f;

    #pragma unroll 1
    for (int k0 = 0; k0 < E_; k0 += 32) {
        __syncthreads();
        // Stage A 128x32 (hi+lo): 512 uint4 units (8 bf16 each), 2 per thread
        #pragma unroll
        for (int i = 0; i < 2; i++) {
            int u   = tid + (i << 8);
            int row = u >> 2;            // 0..127
            int c8  = (u & 3) << 3;      // 0,8,16,24
            size_t so = xoff + (size_t)(m0 + row) * E_ + k0 + c8;
            int   dd  = row * SST + c8;
            *reinterpret_cast<uint4*>(&sAh[dd]) =
                *reinterpret_cast<const uint4*>(&g_h[so]);
            *reinterpret_cast<uint4*>(&sAl[dd]) =
                *reinterpret_cast<const uint4*>(&g_l[so]);
        }
        // Stage B 64x32 (hi+lo): 256 uint4 units, 1 per thread
        {
            int row = tid >> 2;          // 0..63
            int c8  = (tid & 3) << 3;    // 0,8,16,24
            size_t so = WOFF + (size_t)(n0 + row) * E_ + k0 + c8;
            int   dd  = row * SST + c8;
            *reinterpret_cast<uint4*>(&sBh[dd]) =
                *reinterpret_cast<const uint4*>(&g_h[so]);
            *reinterpret_cast<uint4*>(&sBl[dd]) =
                *reinterpret_cast<const uint4*>(&g_l[so]);
        }
        __syncthreads();

        #pragma unroll
        for (int kk = 0; kk < 32; kk += 16) {
            uint32_t ah[2][4], al[2][4], bh[4][2], bl[4][2];
            #pragma unroll
            for (int mi = 0; mi < 2; mi++) {
                int r0 = (wM * 32 + mi * 16 + g) * SST + kk + 2 * tig;
                int r1 = r0 + 8 * SST;
                ah[mi][0] = *reinterpret_cast<const uint32_t*>(&sAh[r0]);
                ah[mi][1] = *reinterpret_cast<const uint32_t*>(&sAh[r1]);
                ah[mi][2] = *reinterpret_cast<const uint32_t*>(&sAh[r0 + 8]);
                ah[mi][3] = *reinterpret_cast<const uint32_t*>(&sAh[r1 + 8]);
                al[mi][0] = *reinterpret_cast<const uint32_t*>(&sAl[r0]);
                al[mi][1] = *reinterpret_cast<const uint32_t*>(&sAl[r1]);
                al[mi][2] = *reinterpret_cast<const uint32_t*>(&sAl[r0 + 8]);
                al[mi][3] = *reinterpret_cast<const uint32_t*>(&sAl[r1 + 8]);
            }
            #pragma unroll
            for (int ni = 0; ni < 4; ni++) {
                int c0 = (wN * 32 + ni * 8 + g) * SST + kk + 2 * tig;
                bh[ni][0] = *reinterpret_cast<const uint32_t*>(&sBh[c0]);
                bh[ni][1] = *reinterpret_cast<const uint32_t*>(&sBh[c0 + 8]);
                bl[ni][0] = *reinterpret_cast<const uint32_t*>(&sBl[c0]);
                bl[ni][1] = *reinterpret_cast<const uint32_t*>(&sBl[c0 + 8]);
            }
            #pragma unroll
            for (int mi = 0; mi < 2; mi++)
                #pragma unroll
                for (int ni = 0; ni < 4; ni++) {
                    mma_bf16(acc[mi][ni], ah[mi], bh[ni]);
                    mma_bf16(acc[mi][ni], ah[mi], bl[ni]);
                    mma_bf16(acc[mi][ni], al[mi], bh[ni]);
                }
        }
    }

    // Epilogue (layout validated in round 6)
    #pragma unroll
    for (int mi = 0; mi < 2; mi++) {
        int row = m0 + wM * 32 + mi * 16 + g;
        #pragma unroll
        for (int ni = 0; ni < 4; ni++) {
            int col = n0 + wN * 32 + ni * 8 + tig * 2;
            float2 bb = *reinterpret_cast<const float2*>(&bias[col]);
            float2 o0 = {acc[mi][ni][0] + bb.x, acc[mi][ni][1] + bb.y};
            float2 o1 = {acc[mi][ni][2] + bb.x, acc[mi][ni][3] + bb.y};
            *reinterpret_cast<float2*>(&P[(size_t)row       * E_ + col]) = o0;
            *reinterpret_cast<float2*>(&P[(size_t)(row + 8) * E_ + col]) = o1;
        }
    }
}

// ---------------------------------------------------------------------------
// Sliding-window attention (round-6 validated version, verbatim).
// Block = (b, h, 64-query tile), 256 threads = 32 pairs x 8 threads.
// ---------------------------------------------------------------------------
__global__ __launch_bounds__(256) void attn_kernel(
        const float* __restrict__ bias,
        float* __restrict__ out) {
    const int QT = 64, ROWS = QT + TAU_ - 1, S = 36;

    __shared__ float sK[ROWS][S];
    __shared__ float sV[ROWS][S];
    __shared__ float sP[QT][33];

    const int tid  = threadIdx.x;
    const int tile = blockIdx.x & 63;
    const int h    = (blockIdx.x >> 6) & 7;
    const int b    = blockIdx.x >> 9;
    const int n0   = tile * QT;
    const int be   = h * HD_;

    const float* Qp = g_proj;
    const float* Kp = g_proj + XSZ;
    const float* Vp = g_proj + 2 * XSZ;

    for (int i = tid; i < ROWS * 8; i += 256) {
        int row = i >> 3, c = i & 7;
        int r = n0 - (TAU_ - 1) + row;
        float4 kv, vv;
        if (r >= 0) {
            size_t off = ((size_t)(b * N_ + r)) * E_ + be;
            kv = reinterpret_cast<const float4*>(&Kp[off])[c];
            vv = reinterpret_cast<const float4*>(&Vp[off])[c];
        } else {
            kv = reinterpret_cast<const float4*>(&bias[be])[c];
            vv = kv;
        }
        *reinterpret_cast<float4*>(&sK[row][c << 2]) = kv;
        *reinterpret_cast<float4*>(&sV[row][c << 2]) = vv;
    }

    const int p    = tid >> 3;
    const int sub  = tid & 7;
    const int lq0  = p << 1;
    const int t0   = sub << 2;

    // Load both Q rows into registers (pre-scaled)
    float4 q0v[8], q1v[8];
    {
        const float* q0p = &Qp[((size_t)(b * N_ + n0 + lq0)) * E_ + be];
        #pragma unroll
        for (int c = 0; c < 8; c++) {
            float4 a = reinterpret_cast<const float4*>(q0p)[c];
            float4 bq = reinterpret_cast<const float4*>(q0p + E_)[c];
            a.x *= SCALING; a.y *= SCALING; a.z *= SCALING; a.w *= SCALING;
            bq.x *= SCALING; bq.y *= SCALING; bq.z *= SCALING; bq.w *= SCALING;
            q0v[c] = a; q1v[c] = bq;
        }
    }
    __syncthreads();

    float s0[4], s1[4];
    #pragma unroll
    for (int j = 0; j < 4; j++) { s0[j] = 0.f; s1[j] = 0.f; }
    #pragma unroll
    for (int j = 0; j < 5; j++) {
        const float* kr = &sK[lq0 + t0 + j][0];
        float d0 = 0.f, d1 = 0.f;
        #pragma unroll
        for (int c = 0; c < 8; c++) {
            float4 kv = *reinterpret_cast<const float4*>(kr + (c << 2));
            d0 += q0v[c].x * kv.x + q0v[c].y * kv.y
                + q0v[c].z * kv.z + q0v[c].w * kv.w;
            d1 += q1v[c].x * kv.x + q1v[c].y * kv.y
                + q1v[c].z * kv.z + q1v[c].w * kv.w;
        }
        if (j < 4) s0[j] = d0;
        if (j > 0) s1[j - 1] = d1;
    }

    float mx0 = fmaxf(fmaxf(s0[0], s0[1]), fmaxf(s0[2], s0[3]));
    float mx1 = fmaxf(fmaxf(s1[0], s1[1]), fmaxf(s1[2], s1[3]));
    #pragma unroll
    for (int m = 1; m <= 4; m <<= 1) {
        mx0 = fmaxf(mx0, __shfl_xor_sync(0xffffffffu, mx0, m));
        mx1 = fmaxf(mx1, __shfl_xor_sync(0xffffffffu, mx1, m));
    }
    float sum0 = 0.f, sum1 = 0.f;
    #pragma unroll
    for (int j = 0; j < 4; j++) {
        s0[j] = __expf(s0[j] - mx0); sum0 += s0[j];
        s1[j] = __expf(s1[j] - mx1); sum1 += s1[j];
    }
    #pragma unroll
    for (int m = 1; m <= 4; m <<= 1) {
        sum0 += __shfl_xor_sync(0xffffffffu, sum0, m);
        sum1 += __shfl_xor_sync(0xffffffffu, sum1, m);
    }
    float inv0 = 1.f / sum0, inv1 = 1.f / sum1;
    #pragma unroll
    for (int j = 0; j < 4; j++) {
        sP[lq0][t0 + j]     = s0[j] * inv0;
        sP[lq0 + 1][t0 + j] = s1[j] * inv1;
    }
    __syncthreads();

    const int d0c = sub << 2;
    float4 o0 = {0.f, 0.f, 0.f, 0.f};
    float4 o1 = {0.f, 0.f, 0.f, 0.f};
    {
        float pr = sP[lq0][0];
        float4 v = *reinterpret_cast<const float4*>(&sV[lq0][d0c]);
        o0.x += pr * v.x; o0.y += pr * v.y; o0.z += pr * v.z; o0.w += pr * v.w;
    }
    #pragma unroll
    for (int r = 1; r < 32; r++) {
        float4 v = *reinterpret_cast<const float4*>(&sV[lq0 + r][d0c]);
        float p0r = sP[lq0][r];
        float p1r = sP[lq0 + 1][r - 1];
        o0.x += p0r * v.x; o0.y += p0r * v.y; o0.z += p0r * v.z; o0.w += p0r * v.w;
        o1.x += p1r * v.x; o1.y += p1r * v.y; o1.z += p1r * v.z; o1.w += p1r * v.w;
    }
    {
        float pr = sP[lq0 + 1][31];
        float4 v = *reinterpret_cast<const float4*>(&sV[lq0 + 32][d0c]);
        o1.x += pr * v.x; o1.y += pr * v.y; o1.z += pr * v.z; o1.w += pr * v.w;
    }

    float* orow = &out[((size_t)(b * N_ + n0 + lq0)) * E_ + be + d0c];
    *reinterpret_cast<float4*>(orow)      = o0;
    *reinterpret_cast<float4*>(orow + E_) = o1;
}

// ---------------------------------------------------------------------------
// Launch
// ---------------------------------------------------------------------------
extern "C" void kernel_launch(void* const* d_in, const int* in_sizes, int n_in,
                              void* d_out, int out_size) {
    const float* query = (const float*)d_in[0];
    const float* key   = (const float*)d_in[1];
    const float* value = (const float*)d_in[2];
    const float* W     = (const float*)d_in[3];
    const float* bias  = (const float*)d_in[4];
    float* out = (float*)d_out;

    int convBlocks = (int)((TOT_ELEMS / 4 + 255) / 256);
    convert_kernel<<<convBlocks, 256>>>(query, key, value, W);

    dim3 gProj(E_ / 64, M_ / 128, 3);   // (4, 64, 3)
    proj_kernel<<<gProj, 256>>>(bias);

    attn_kernel<<<B_ * H_ * (N_ / 64), 256>>>(bias, out);
}

// round 10
// speedup vs baseline: 1.6372x; 1.6372x over previous
#include <cuda_runtime.h>
#include <cuda_bf16.h>
#include <cstdint>

// Problem constants
#define B_   2
#define N_   4096
#define E_   256
#define H_   8
#define TAU_ 32
#define HD_  32
#define M_   (B_ * N_)
#define SCALING 0.17677669529663687f
#define XSZ  ((size_t)M_ * E_)

// Scratch: projected Q, K, V (fp32)
__device__ float g_proj[3 * XSZ];

// ---------------------------------------------------------------------------
// bf16 split helpers: x = hi + lo (both bf16). 3 MMA passes (hh + hl + lh).
// ---------------------------------------------------------------------------
__device__ __forceinline__ void split_bf16(float x, __nv_bfloat16& h,
                                           __nv_bfloat16& l) {
    h = __float2bfloat16(x);
    l = __float2bfloat16(x - __bfloat162float(h));
}

__device__ __forceinline__ void mma_bf16(float c[4], const uint32_t a[4],
                                         const uint32_t b[2]) {
    asm volatile(
        "mma.sync.aligned.m16n8k16.row.col.f32.bf16.bf16.f32 "
        "{%0,%1,%2,%3}, {%4,%5,%6,%7}, {%8,%9}, {%0,%1,%2,%3};"
        : "+f"(c[0]), "+f"(c[1]), "+f"(c[2]), "+f"(c[3])
        : "r"(a[0]), "r"(a[1]), "r"(a[2]), "r"(a[3]), "r"(b[0]), "r"(b[1]));
}

// ---------------------------------------------------------------------------
// Projection GEMM (round-6 validated, 43.6us): P = X @ W^T + bias.
// Block 128x64, BK=32, 8 warps (4M x 2N), warp tile 32x32, split-3 bf16.
// ---------------------------------------------------------------------------
#define SA_STRIDE 36

__global__ __launch_bounds__(256) void proj_kernel(
        const float* __restrict__ Q,
        const float* __restrict__ K,
        const float* __restrict__ V,
        const float* __restrict__ W,
        const float* __restrict__ bias) {
    __shared__ __nv_bfloat16 sAh[128 * SA_STRIDE];
    __shared__ __nv_bfloat16 sAl[128 * SA_STRIDE];
    __shared__ __nv_bfloat16 sBh[64 * SA_STRIDE];
    __shared__ __nv_bfloat16 sBl[64 * SA_STRIDE];

    const float* X = (blockIdx.z == 0) ? Q : (blockIdx.z == 1 ? K : V);
    float* P = g_proj + (size_t)blockIdx.z * XSZ;

    const int tid  = threadIdx.x;
    const int m0   = blockIdx.y << 7;
    const int n0   = blockIdx.x << 6;
    const int lane = tid & 31;
    const int warp = tid >> 5;
    const int g    = lane >> 2;
    const int tig  = lane & 3;
    const int wM   = warp & 3;
    const int wN   = warp >> 2;

    float acc[2][4][4];
    #pragma unroll
    for (int mi = 0; mi < 2; mi++)
        #pragma unroll
        for (int ni = 0; ni < 4; ni++)
            #pragma unroll
            for (int r = 0; r < 4; r++) acc[mi][ni][r] = 0.f;

    #pragma unroll 1
    for (int k0 = 0; k0 < E_; k0 += 32) {
        __syncthreads();
        #pragma unroll
        for (int i = 0; i < 4; i++) {
            int e   = tid + (i << 8);
            int row = e >> 3;
            int c4  = (e & 7) << 2;
            float4 v = *reinterpret_cast<const float4*>(
                &X[(size_t)(m0 + row) * E_ + k0 + c4]);
            __nv_bfloat16 h[4], l[4];
            split_bf16(v.x, h[0], l[0]);
            split_bf16(v.y, h[1], l[1]);
            split_bf16(v.z, h[2], l[2]);
            split_bf16(v.w, h[3], l[3]);
            int o = row * SA_STRIDE + c4;
            *reinterpret_cast<ushort4*>(&sAh[o]) =
                make_ushort4(__bfloat16_as_ushort(h[0]), __bfloat16_as_ushort(h[1]),
                             __bfloat16_as_ushort(h[2]), __bfloat16_as_ushort(h[3]));
            *reinterpret_cast<ushort4*>(&sAl[o]) =
                make_ushort4(__bfloat16_as_ushort(l[0]), __bfloat16_as_ushort(l[1]),
                             __bfloat16_as_ushort(l[2]), __bfloat16_as_ushort(l[3]));
        }
        #pragma unroll
        for (int i = 0; i < 2; i++) {
            int e   = tid + (i << 8);
            int row = e >> 3;
            int c4  = (e & 7) << 2;
            float4 v = *reinterpret_cast<const float4*>(
                &W[(size_t)(n0 + row) * E_ + k0 + c4]);
            __nv_bfloat16 h[4], l[4];
            split_bf16(v.x, h[0], l[0]);
            split_bf16(v.y, h[1], l[1]);
            split_bf16(v.z, h[2], l[2]);
            split_bf16(v.w, h[3], l[3]);
            int o = row * SA_STRIDE + c4;
            *reinterpret_cast<ushort4*>(&sBh[o]) =
                make_ushort4(__bfloat16_as_ushort(h[0]), __bfloat16_as_ushort(h[1]),
                             __bfloat16_as_ushort(h[2]), __bfloat16_as_ushort(h[3]));
            *reinterpret_cast<ushort4*>(&sBl[o]) =
                make_ushort4(__bfloat16_as_ushort(l[0]), __bfloat16_as_ushort(l[1]),
                             __bfloat16_as_ushort(l[2]), __bfloat16_as_ushort(l[3]));
        }
        __syncthreads();

        #pragma unroll
        for (int kk = 0; kk < 32; kk += 16) {
            uint32_t ah[2][4], al[2][4], bh[4][2], bl[4][2];
            #pragma unroll
            for (int mi = 0; mi < 2; mi++) {
                int r0 = (wM * 32 + mi * 16 + g) * SA_STRIDE + kk + 2 * tig;
                int r1 = r0 + 8 * SA_STRIDE;
                ah[mi][0] = *reinterpret_cast<const uint32_t*>(&sAh[r0]);
                ah[mi][1] = *reinterpret_cast<const uint32_t*>(&sAh[r1]);
                ah[mi][2] = *reinterpret_cast<const uint32_t*>(&sAh[r0 + 8]);
                ah[mi][3] = *reinterpret_cast<const uint32_t*>(&sAh[r1 + 8]);
                al[mi][0] = *reinterpret_cast<const uint32_t*>(&sAl[r0]);
                al[mi][1] = *reinterpret_cast<const uint32_t*>(&sAl[r1]);
                al[mi][2] = *reinterpret_cast<const uint32_t*>(&sAl[r0 + 8]);
                al[mi][3] = *reinterpret_cast<const uint32_t*>(&sAl[r1 + 8]);
            }
            #pragma unroll
            for (int ni = 0; ni < 4; ni++) {
                int c0 = (wN * 32 + ni * 8 + g) * SA_STRIDE + kk + 2 * tig;
                bh[ni][0] = *reinterpret_cast<const uint32_t*>(&sBh[c0]);
                bh[ni][1] = *reinterpret_cast<const uint32_t*>(&sBh[c0 + 8]);
                bl[ni][0] = *reinterpret_cast<const uint32_t*>(&sBl[c0]);
                bl[ni][1] = *reinterpret_cast<const uint32_t*>(&sBl[c0 + 8]);
            }
            #pragma unroll
            for (int mi = 0; mi < 2; mi++)
                #pragma unroll
                for (int ni = 0; ni < 4; ni++) {
                    mma_bf16(acc[mi][ni], ah[mi], bh[ni]);
                    mma_bf16(acc[mi][ni], ah[mi], bl[ni]);
                    mma_bf16(acc[mi][ni], al[mi], bh[ni]);
                }
        }
    }

    #pragma unroll
    for (int mi = 0; mi < 2; mi++) {
        int row = m0 + wM * 32 + mi * 16 + g;
        #pragma unroll
        for (int ni = 0; ni < 4; ni++) {
            int col = n0 + wN * 32 + ni * 8 + tig * 2;
            float2 bb = *reinterpret_cast<const float2*>(&bias[col]);
            float2 o0 = {acc[mi][ni][0] + bb.x, acc[mi][ni][1] + bb.y};
            float2 o1 = {acc[mi][ni][2] + bb.x, acc[mi][ni][3] + bb.y};
            *reinterpret_cast<float2*>(&P[(size_t)row       * E_ + col]) = o0;
            *reinterpret_cast<float2*>(&P[(size_t)(row + 8) * E_ + col]) = o1;
        }
    }
}

// ---------------------------------------------------------------------------
// Sliding-window attention, query-paired, register diet: Q consumed in
// 4 x 8-dim chunks from gmem (no 64-reg preload). 256 thr = 32 pairs x 8.
// ---------------------------------------------------------------------------
__global__ __launch_bounds__(256) void attn_kernel(
        const float* __restrict__ bias,
        float* __restrict__ out) {
    const int QT = 64, ROWS = QT + TAU_ - 1, S = 36;

    __shared__ float sK[ROWS][S];
    __shared__ float sV[ROWS][S];
    __shared__ float sP[QT][33];

    const int tid  = threadIdx.x;
    const int tile = blockIdx.x & 63;
    const int h    = (blockIdx.x >> 6) & 7;
    const int b    = blockIdx.x >> 9;
    const int n0   = tile * QT;
    const int be   = h * HD_;

    const float* Qp = g_proj;
    const float* Kp = g_proj + XSZ;
    const float* Vp = g_proj + 2 * XSZ;

    // Stage K/V window rows [n0-31, n0+63]; pre-sequence rows = bias vector.
    for (int i = tid; i < ROWS * 8; i += 256) {
        int row = i >> 3, c = i & 7;
        int r = n0 - (TAU_ - 1) + row;
        float4 kv, vv;
        if (r >= 0) {
            size_t off = ((size_t)(b * N_ + r)) * E_ + be;
            kv = reinterpret_cast<const float4*>(&Kp[off])[c];
            vv = reinterpret_cast<const float4*>(&Vp[off])[c];
        } else {
            kv = reinterpret_cast<const float4*>(&bias[be])[c];
            vv = kv;
        }
        *reinterpret_cast<float4*>(&sK[row][c << 2]) = kv;
        *reinterpret_cast<float4*>(&sV[row][c << 2]) = vv;
    }
    __syncthreads();

    const int p   = tid >> 3;        // pair 0..31
    const int sub = tid & 7;         // 0..7
    const int lq0 = p << 1;
    const int t0  = sub << 2;

    // Scores chunked over 4 x 8-dim pieces. Row j = sK[lq0+t0+j]:
    // d0[0..3] -> query lq0 scores t0..t0+3; d1[1..4] -> query lq0+1.
    float d0[5] = {0.f, 0.f, 0.f, 0.f, 0.f};
    float d1[5] = {0.f, 0.f, 0.f, 0.f, 0.f};
    const float* q0p = &Qp[((size_t)(b * N_ + n0 + lq0)) * E_ + be];
    #pragma unroll
    for (int c = 0; c < 4; c++) {
        float4 qa0 = *reinterpret_cast<const float4*>(q0p + (c << 3));
        float4 qa1 = *reinterpret_cast<const float4*>(q0p + (c << 3) + 4);
        float4 qb0 = *reinterpret_cast<const float4*>(q0p + E_ + (c << 3));
        float4 qb1 = *reinterpret_cast<const float4*>(q0p + E_ + (c << 3) + 4);
        #pragma unroll
        for (int j = 0; j < 5; j++) {
            const float* kr = &sK[lq0 + t0 + j][c << 3];
            float4 k0v = *reinterpret_cast<const float4*>(kr);
            float4 k1v = *reinterpret_cast<const float4*>(kr + 4);
            d0[j] += qa0.x * k0v.x + qa0.y * k0v.y + qa0.z * k0v.z + qa0.w * k0v.w
                   + qa1.x * k1v.x + qa1.y * k1v.y + qa1.z * k1v.z + qa1.w * k1v.w;
            d1[j] += qb0.x * k0v.x + qb0.y * k0v.y + qb0.z * k0v.z + qb0.w * k0v.w
                   + qb1.x * k1v.x + qb1.y * k1v.y + qb1.z * k1v.z + qb1.w * k1v.w;
        }
    }
    float s0[4], s1[4];
    #pragma unroll
    for (int j = 0; j < 4; j++) {
        s0[j] = d0[j] * SCALING;
        s1[j] = d1[j + 1] * SCALING;
    }

    // Softmax across the 8 lanes of the pair-group
    float mx0 = fmaxf(fmaxf(s0[0], s0[1]), fmaxf(s0[2], s0[3]));
    float mx1 = fmaxf(fmaxf(s1[0], s1[1]), fmaxf(s1[2], s1[3]));
    #pragma unroll
    for (int m = 1; m <= 4; m <<= 1) {
        mx0 = fmaxf(mx0, __shfl_xor_sync(0xffffffffu, mx0, m));
        mx1 = fmaxf(mx1, __shfl_xor_sync(0xffffffffu, mx1, m));
    }
    float sum0 = 0.f, sum1 = 0.f;
    #pragma unroll
    for (int j = 0; j < 4; j++) {
        s0[j] = __expf(s0[j] - mx0); sum0 += s0[j];
        s1[j] = __expf(s1[j] - mx1); sum1 += s1[j];
    }
    #pragma unroll
    for (int m = 1; m <= 4; m <<= 1) {
        sum0 += __shfl_xor_sync(0xffffffffu, sum0, m);
        sum1 += __shfl_xor_sync(0xffffffffu, sum1, m);
    }
    float inv0 = 1.f / sum0, inv1 = 1.f / sum1;
    #pragma unroll
    for (int j = 0; j < 4; j++) {
        sP[lq0][t0 + j]     = s0[j] * inv0;
        sP[lq0 + 1][t0 + j] = s1[j] * inv1;
    }
    __syncthreads();

    // Output: dims [4*sub, 4*sub+4) for both queries.
    const int d0c = sub << 2;
    float4 o0 = {0.f, 0.f, 0.f, 0.f};
    float4 o1 = {0.f, 0.f, 0.f, 0.f};
    {
        float pr = sP[lq0][0];
        float4 v = *reinterpret_cast<const float4*>(&sV[lq0][d0c]);
        o0.x += pr * v.x; o0.y += pr * v.y; o0.z += pr * v.z; o0.w += pr * v.w;
    }
    #pragma unroll
    for (int r = 1; r < 32; r++) {
        float4 v = *reinterpret_cast<const float4*>(&sV[lq0 + r][d0c]);
        float p0r = sP[lq0][r];
        float p1r = sP[lq0 + 1][r - 1];
        o0.x += p0r * v.x; o0.y += p0r * v.y; o0.z += p0r * v.z; o0.w += p0r * v.w;
        o1.x += p1r * v.x; o1.y += p1r * v.y; o1.z += p1r * v.z; o1.w += p1r * v.w;
    }
    {
        float pr = sP[lq0 + 1][31];
        float4 v = *reinterpret_cast<const float4*>(&sV[lq0 + 32][d0c]);
        o1.x += pr * v.x; o1.y += pr * v.y; o1.z += pr * v.z; o1.w += pr * v.w;
    }

    float* orow = &out[((size_t)(b * N_ + n0 + lq0)) * E_ + be + d0c];
    *reinterpret_cast<float4*>(orow)      = o0;
    *reinterpret_cast<float4*>(orow + E_) = o1;
}

// ---------------------------------------------------------------------------
// Launch
// ---------------------------------------------------------------------------
extern "C" void kernel_launch(void* const* d_in, const int* in_sizes, int n_in,
                              void* d_out, int out_size) {
    const float* query = (const float*)d_in[0];
    const float* key   = (const float*)d_in[1];
    const float* value = (const float*)d_in[2];
    const float* W     = (const float*)d_in[3];
    const float* bias  = (const float*)d_in[4];
    float* out = (float*)d_out;

    dim3 gProj(E_ / 64, M_ / 128, 3);   // (4, 64, 3)
    proj_kernel<<<gProj, 256>>>(query, key, value, W, bias);

    attn_kernel<<<B_ * H_ * (N_ / 64), 256>>>(bias, out);
}

// round 13
// speedup vs baseline: 1.9319x; 1.1800x over previous
#include <cuda_runtime.h>
#include <cuda_bf16.h>
#include <cstdint>

// Problem constants
#define B_   2
#define N_   4096
#define E_   256
#define H_   8
#define TAU_ 32
#define HD_  32
#define M_   (B_ * N_)
#define SCALING 0.17677669529663687f
#define XSZ  ((size_t)M_ * E_)

// Scratch: projected Q, K, V (fp32)
__device__ float g_proj[3 * XSZ];

// ---------------------------------------------------------------------------
__device__ __forceinline__ uint32_t smem_u32(const void* p) {
    uint32_t a;
    asm("{ .reg .u64 t; cvta.to.shared.u64 t, %1; cvt.u32.u64 %0, t; }"
        : "=r"(a) : "l"(p));
    return a;
}

__device__ __forceinline__ void split_bf16(float x, __nv_bfloat16& h,
                                           __nv_bfloat16& l) {
    h = __float2bfloat16(x);
    l = __float2bfloat16(x - __bfloat162float(h));
}

__device__ __forceinline__ void mma_bf16(float c[4], const uint32_t a[4],
                                         const uint32_t b[2]) {
    asm volatile(
        "mma.sync.aligned.m16n8k16.row.col.f32.bf16.bf16.f32 "
        "{%0,%1,%2,%3}, {%4,%5,%6,%7}, {%8,%9}, {%0,%1,%2,%3};"
        : "+f"(c[0]), "+f"(c[1]), "+f"(c[2]), "+f"(c[3])
        : "r"(a[0]), "r"(a[1]), "r"(a[2]), "r"(a[3]), "r"(b[0]), "r"(b[1]));
}

#define LDSM_X4(R0, R1, R2, R3, ADDR)                                          \
    asm volatile("ldmatrix.sync.aligned.m8n8.x4.shared.b16 {%0,%1,%2,%3}, [%4];" \
                 : "=r"(R0), "=r"(R1), "=r"(R2), "=r"(R3) : "r"(ADDR))

// ---------------------------------------------------------------------------
// Projection GEMM: P = X @ W^T + bias (M=8192, N=256, K=256), z selects X.
// Block 128x64, BK=32, 8 warps (4M x 2N), warp tile 32x32, split-3 bf16.
// Staging: round-6-validated inline split (ushort4, 4-col steps).
// Fragments: ldmatrix.x4; SST=40 -> LDSM rows tile all 32 banks exactly.
// ---------------------------------------------------------------------------
#define SST 40   // bf16 elems per smem row (32 + 8 pad)

__global__ __launch_bounds__(256) void proj_kernel(
        const float* __restrict__ Q,
        const float* __restrict__ K,
        const float* __restrict__ V,
        const float* __restrict__ W,
        const float* __restrict__ bias) {
    __shared__ alignas(16) __nv_bfloat16 sAh[128 * SST];
    __shared__ alignas(16) __nv_bfloat16 sAl[128 * SST];
    __shared__ alignas(16) __nv_bfloat16 sBh[64 * SST];
    __shared__ alignas(16) __nv_bfloat16 sBl[64 * SST];

    const float* X = (blockIdx.z == 0) ? Q : (blockIdx.z == 1 ? K : V);
    float* P = g_proj + (size_t)blockIdx.z * XSZ;

    const int tid  = threadIdx.x;
    const int m0   = blockIdx.y << 7;
    const int n0   = blockIdx.x << 6;
    const int lane = tid & 31;
    const int warp = tid >> 5;
    const int g    = lane >> 2;
    const int tig  = lane & 3;
    const int wM   = warp & 3;
    const int wN   = warp >> 2;

    const uint32_t bAh = smem_u32(sAh), bAl = smem_u32(sAl);
    const uint32_t bBh = smem_u32(sBh), bBl = smem_u32(sBl);
    // ldmatrix per-lane element offsets
    const int aoff = (lane & 15) * SST + ((lane >> 4) << 3);
    const int boff = ((lane & 7) + ((lane & 16) >> 1)) * SST
                   + (((lane >> 3) & 1) << 3);

    float acc[2][4][4];
    #pragma unroll
    for (int mi = 0; mi < 2; mi++)
        #pragma unroll
        for (int ni = 0; ni < 4; ni++)
            #pragma unroll
            for (int r = 0; r < 4; r++) acc[mi][ni][r] = 0.f;

    #pragma unroll 1
    for (int k0 = 0; k0 < E_; k0 += 32) {
        __syncthreads();
        // Stage A chunk 128x32: inline split, 4 float4 per thread
        #pragma unroll
        for (int i = 0; i < 4; i++) {
            int e   = tid + (i << 8);
            int row = e >> 3;
            int c4  = (e & 7) << 2;
            float4 v = *reinterpret_cast<const float4*>(
                &X[(size_t)(m0 + row) * E_ + k0 + c4]);
            __nv_bfloat16 h[4], l[4];
            split_bf16(v.x, h[0], l[0]);
            split_bf16(v.y, h[1], l[1]);
            split_bf16(v.z, h[2], l[2]);
            split_bf16(v.w, h[3], l[3]);
            int o = row * SST + c4;
            *reinterpret_cast<ushort4*>(&sAh[o]) =
                make_ushort4(__bfloat16_as_ushort(h[0]), __bfloat16_as_ushort(h[1]),
                             __bfloat16_as_ushort(h[2]), __bfloat16_as_ushort(h[3]));
            *reinterpret_cast<ushort4*>(&sAl[o]) =
                make_ushort4(__bfloat16_as_ushort(l[0]), __bfloat16_as_ushort(l[1]),
                             __bfloat16_as_ushort(l[2]), __bfloat16_as_ushort(l[3]));
        }
        // Stage B chunk 64x32: 2 float4 per thread
        #pragma unroll
        for (int i = 0; i < 2; i++) {
            int e   = tid + (i << 8);
            int row = e >> 3;
            int c4  = (e & 7) << 2;
            float4 v = *reinterpret_cast<const float4*>(
                &W[(size_t)(n0 + row) * E_ + k0 + c4]);
            __nv_bfloat16 h[4], l[4];
            split_bf16(v.x, h[0], l[0]);
            split_bf16(v.y, h[1], l[1]);
            split_bf16(v.z, h[2], l[2]);
            split_bf16(v.w, h[3], l[3]);
            int o = row * SST + c4;
            *reinterpret_cast<ushort4*>(&sBh[o]) =
                make_ushort4(__bfloat16_as_ushort(h[0]), __bfloat16_as_ushort(h[1]),
                             __bfloat16_as_ushort(h[2]), __bfloat16_as_ushort(h[3]));
            *reinterpret_cast<ushort4*>(&sBl[o]) =
                make_ushort4(__bfloat16_as_ushort(l[0]), __bfloat16_as_ushort(l[1]),
                             __bfloat16_as_ushort(l[2]), __bfloat16_as_ushort(l[3]));
        }
        __syncthreads();

        #pragma unroll
        for (int kk = 0; kk < 32; kk += 16) {
            uint32_t ah[2][4], al[2][4], bh[4][2], bl[4][2];
            #pragma unroll
            for (int mi = 0; mi < 2; mi++) {
                uint32_t ea = 2u * (uint32_t)((wM * 32 + mi * 16) * SST + aoff + kk);
                LDSM_X4(ah[mi][0], ah[mi][1], ah[mi][2], ah[mi][3], bAh + ea);
                LDSM_X4(al[mi][0], al[mi][1], al[mi][2], al[mi][3], bAl + ea);
            }
            #pragma unroll
            for (int p = 0; p < 2; p++) {
                uint32_t eb = 2u * (uint32_t)((wN * 32 + p * 16) * SST + boff + kk);
                LDSM_X4(bh[2*p][0], bh[2*p][1], bh[2*p+1][0], bh[2*p+1][1], bBh + eb);
                LDSM_X4(bl[2*p][0], bl[2*p][1], bl[2*p+1][0], bl[2*p+1][1], bBl + eb);
            }
            #pragma unroll
            for (int mi = 0; mi < 2; mi++)
                #pragma unroll
                for (int ni = 0; ni < 4; ni++) {
                    mma_bf16(acc[mi][ni], ah[mi], bh[ni]);
                    mma_bf16(acc[mi][ni], ah[mi], bl[ni]);
                    mma_bf16(acc[mi][ni], al[mi], bh[ni]);
                }
        }
    }

    // Epilogue (layout validated in round 6)
    #pragma unroll
    for (int mi = 0; mi < 2; mi++) {
        int row = m0 + wM * 32 + mi * 16 + g;
        #pragma unroll
        for (int ni = 0; ni < 4; ni++) {
            int col = n0 + wN * 32 + ni * 8 + tig * 2;
            float2 bb = *reinterpret_cast<const float2*>(&bias[col]);
            float2 o0 = {acc[mi][ni][0] + bb.x, acc[mi][ni][1] + bb.y};
            float2 o1 = {acc[mi][ni][2] + bb.x, acc[mi][ni][3] + bb.y};
            *reinterpret_cast<float2*>(&P[(size_t)row       * E_ + col]) = o0;
            *reinterpret_cast<float2*>(&P[(size_t)(row + 8) * E_ + col]) = o1;
        }
    }
}

// ---------------------------------------------------------------------------
// Sliding-window attention (round-10 validated, verbatim).
// ---------------------------------------------------------------------------
__global__ __launch_bounds__(256) void attn_kernel(
        const float* __restrict__ bias,
        float* __restrict__ out) {
    const int QT = 64, ROWS = QT + TAU_ - 1, S = 36;

    __shared__ float sK[ROWS][S];
    __shared__ float sV[ROWS][S];
    __shared__ float sP[QT][33];

    const int tid  = threadIdx.x;
    const int tile = blockIdx.x & 63;
    const int h    = (blockIdx.x >> 6) & 7;
    const int b    = blockIdx.x >> 9;
    const int n0   = tile * QT;
    const int be   = h * HD_;

    const float* Qp = g_proj;
    const float* Kp = g_proj + XSZ;
    const float* Vp = g_proj + 2 * XSZ;

    for (int i = tid; i < ROWS * 8; i += 256) {
        int row = i >> 3, c = i & 7;
        int r = n0 - (TAU_ - 1) + row;
        float4 kv, vv;
        if (r >= 0) {
            size_t off = ((size_t)(b * N_ + r)) * E_ + be;
            kv = reinterpret_cast<const float4*>(&Kp[off])[c];
            vv = reinterpret_cast<const float4*>(&Vp[off])[c];
        } else {
            kv = reinterpret_cast<const float4*>(&bias[be])[c];
            vv = kv;
        }
        *reinterpret_cast<float4*>(&sK[row][c << 2]) = kv;
        *reinterpret_cast<float4*>(&sV[row][c << 2]) = vv;
    }
    __syncthreads();

    const int p   = tid >> 3;
    const int sub = tid & 7;
    const int lq0 = p << 1;
    const int t0  = sub << 2;

    float d0[5] = {0.f, 0.f, 0.f, 0.f, 0.f};
    float d1[5] = {0.f, 0.f, 0.f, 0.f, 0.f};
    const float* q0p = &Qp[((size_t)(b * N_ + n0 + lq0)) * E_ + be];
    #pragma unroll
    for (int c = 0; c < 4; c++) {
        float4 qa0 = *reinterpret_cast<const float4*>(q0p + (c << 3));
        float4 qa1 = *reinterpret_cast<const float4*>(q0p + (c << 3) + 4);
        float4 qb0 = *reinterpret_cast<const float4*>(q0p + E_ + (c << 3));
        float4 qb1 = *reinterpret_cast<const float4*>(q0p + E_ + (c << 3) + 4);
        #pragma unroll
        for (int j = 0; j < 5; j++) {
            const float* kr = &sK[lq0 + t0 + j][c << 3];
            float4 k0v = *reinterpret_cast<const float4*>(kr);
            float4 k1v = *reinterpret_cast<const float4*>(kr + 4);
            d0[j] += qa0.x * k0v.x + qa0.y * k0v.y + qa0.z * k0v.z + qa0.w * k0v.w
                   + qa1.x * k1v.x + qa1.y * k1v.y + qa1.z * k1v.z + qa1.w * k1v.w;
            d1[j] += qb0.x * k0v.x + qb0.y * k0v.y + qb0.z * k0v.z + qb0.w * k0v.w
                   + qb1.x * k1v.x + qb1.y * k1v.y + qb1.z * k1v.z + qb1.w * k1v.w;
        }
    }
    float s0[4], s1[4];
    #pragma unroll
    for (int j = 0; j < 4; j++) {
        s0[j] = d0[j] * SCALING;
        s1[j] = d1[j + 1] * SCALING;
    }

    float mx0 = fmaxf(fmaxf(s0[0], s0[1]), fmaxf(s0[2], s0[3]));
    float mx1 = fmaxf(fmaxf(s1[0], s1[1]), fmaxf(s1[2], s1[3]));
    #pragma unroll
    for (int m = 1; m <= 4; m <<= 1) {
        mx0 = fmaxf(mx0, __shfl_xor_sync(0xffffffffu, mx0, m));
        mx1 = fmaxf(mx1, __shfl_xor_sync(0xffffffffu, mx1, m));
    }
    float sum0 = 0.f, sum1 = 0.f;
    #pragma unroll
    for (int j = 0; j < 4; j++) {
        s0[j] = __expf(s0[j] - mx0); sum0 += s0[j];
        s1[j] = __expf(s1[j] - mx1); sum1 += s1[j];
    }
    #pragma unroll
    for (int m = 1; m <= 4; m <<= 1) {
        sum0 += __shfl_xor_sync(0xffffffffu, sum0, m);
        sum1 += __shfl_xor_sync(0xffffffffu, sum1, m);
    }
    float inv0 = 1.f / sum0, inv1 = 1.f / sum1;
    #pragma unroll
    for (int j = 0; j < 4; j++) {
        sP[lq0][t0 + j]     = s0[j] * inv0;
        sP[lq0 + 1][t0 + j] = s1[j] * inv1;
    }
    __syncthreads();

    const int d0c = sub << 2;
    float4 o0 = {0.f, 0.f, 0.f, 0.f};
    float4 o1 = {0.f, 0.f, 0.f, 0.f};
    {
        float pr = sP[lq0][0];
        float4 v = *reinterpret_cast<const float4*>(&sV[lq0][d0c]);
        o0.x += pr * v.x; o0.y += pr * v.y; o0.z += pr * v.z; o0.w += pr * v.w;
    }
    #pragma unroll
    for (int r = 1; r < 32; r++) {
        float4 v = *reinterpret_cast<const float4*>(&sV[lq0 + r][d0c]);
        float p0r = sP[lq0][r];
        float p1r = sP[lq0 + 1][r - 1];
        o0.x += p0r * v.x; o0.y += p0r * v.y; o0.z += p0r * v.z; o0.w += p0r * v.w;
        o1.x += p1r * v.x; o1.y += p1r * v.y; o1.z += p1r * v.z; o1.w += p1r * v.w;
    }
    {
        float pr = sP[lq0 + 1][31];
        float4 v = *reinterpret_cast<const float4*>(&sV[lq0 + 32][d0c]);
        o1.x += pr * v.x; o1.y += pr * v.y; o1.z += pr * v.z; o1.w += pr * v.w;
    }

    float* orow = &out[((size_t)(b * N_ + n0 + lq0)) * E_ + be + d0c];
    *reinterpret_cast<float4*>(orow)      = o0;
    *reinterpret_cast<float4*>(orow + E_) = o1;
}

// ---------------------------------------------------------------------------
// Launch
// ---------------------------------------------------------------------------
extern "C" void kernel_launch(void* const* d_in, const int* in_sizes, int n_in,
                              void* d_out, int out_size) {
    const float* query = (const float*)d_in[0];
    const float* key   = (const float*)d_in[1];
    const float* value = (const float*)d_in[2];
    const float* W     = (const float*)d_in[3];
    const float* bias  = (const float*)d_in[4];
    float* out = (float*)d_out;

    dim3 gProj(E_ / 64, M_ / 128, 3);   // (4, 64, 3)
    proj_kernel<<<gProj, 256>>>(query, key, value, W, bias);

    attn_kernel<<<B_ * H_ * (N_ / 64), 256>>>(bias, out);
}